// round 5
// baseline (speedup 1.0000x reference)
#include <cuda_runtime.h>

// HOAF: per-group (G=32, cpg=8) polynomial expansion (164 features) +
// per-group 8x164 matvec. B=16, C=256, HW=3136.
//
// R4: R3's 4-unit version spilled (regs=128, 1.9GB local traffic, 339us).
// Revert to 2 pixel-units (batches b, b+8) like R2 (109us, fma=54, L1=53,
// occ=20 -> issue-starved), but split the 8 outputs into 2 passes of 4 to
// shrink acc regs 32->16, targeting ~85 regs so 3 CTAs/SM fit (21 warps).
// Deg2/3 muls recomputed per pass (+10.6% fma ops). Predicted: occ ~33%,
// fma ~75%, L1 ~72%, ~80us.

typedef unsigned long long u64;

#define HW   3136
#define TPB  224

__device__ __forceinline__ u64 fma2(u64 a, u64 b, u64 c) {
    u64 d;
    asm("fma.rn.f32x2 %0, %1, %2, %3;" : "=l"(d) : "l"(a), "l"(b), "l"(c));
    return d;
}
__device__ __forceinline__ u64 mul2(u64 a, u64 b) {
    u64 d;
    asm("mul.rn.f32x2 %0, %1, %2;" : "=l"(d) : "l"(a), "l"(b));
    return d;
}

__global__ __launch_bounds__(TPB, 3) void hoaf_kernel(
    const float* __restrict__ x,
    const float* __restrict__ w1, const float* __restrict__ b1,
    const float* __restrict__ w2, const float* __restrict__ b2,
    const float* __restrict__ w3, const float* __restrict__ b3,
    float* __restrict__ out)
{
    // [half][feature][output-in-half], each entry (w,w) packed
    __shared__ alignas(16) u64 wdup[2][164][4];
    __shared__ u64 biasdup[2][4];

    const int tid = threadIdx.x;
    const int g = blockIdx.y;

    // Stage this group's weights, duplicated into both f32x2 lanes.
    // Feature f: [0,8)=deg1, [8,44)=deg2 (triu), [44,164)=deg3 (sorted
    // triples) -- identical ordering to the reference.
    for (int idx = tid; idx < 1312; idx += TPB) {
        const int f = idx >> 3;
        const int o = idx & 7;
        float v;
        if (f < 8)        v = w1[(g * 8 + o) * 8   + f];
        else if (f < 44)  v = w2[(g * 8 + o) * 36  + (f - 8)];
        else              v = w3[(g * 8 + o) * 120 + (f - 44)];
        const unsigned int u = __float_as_uint(v);
        wdup[o >> 2][f][o & 3] = ((u64)u << 32) | u;
    }
    if (tid < 8) {
        const float v = b1[g * 8 + tid] + b2[g * 8 + tid] + b3[g * 8 + tid];
        const unsigned int u = __float_as_uint(v);
        biasdup[tid >> 2][tid & 3] = ((u64)u << 32) | u;
    }
    __syncthreads();

    // Pixel pair p in batches z and z+8.
    const int p = (blockIdx.x * TPB + tid) * 2;
    const size_t gbase = ((size_t)blockIdx.z * 256 + (size_t)g * 8) * HW + p;
    const size_t bstr  = (size_t)8 * 256 * HW;

    u64 XA[8], XB[8];
#pragma unroll
    for (int k = 0; k < 8; k++) {
        XA[k] = *(const u64*)(x + gbase + (size_t)k * HW);
        XB[k] = *(const u64*)(x + gbase + bstr + (size_t)k * HW);
    }

#pragma unroll
    for (int pass = 0; pass < 2; pass++) {
        u64 accA[4], accB[4];
#pragma unroll
        for (int o = 0; o < 4; o++) {
            accA[o] = biasdup[pass][o];
            accB[o] = accA[o];
        }

        // One feature (2 units) into 4 outputs: 2 LDS.128, 8 FFMA2.
        auto accF = [&](int f, u64 fA, u64 fB) {
            const ulonglong2* wp = (const ulonglong2*)wdup[pass][f];
            const ulonglong2 wa = wp[0], wb = wp[1];
            accA[0] = fma2(fA, wa.x, accA[0]);
            accB[0] = fma2(fB, wa.x, accB[0]);
            accA[1] = fma2(fA, wa.y, accA[1]);
            accB[1] = fma2(fB, wa.y, accB[1]);
            accA[2] = fma2(fA, wb.x, accA[2]);
            accB[2] = fma2(fB, wb.x, accB[2]);
            accA[3] = fma2(fA, wb.y, accA[3]);
            accB[3] = fma2(fB, wb.y, accB[3]);
        };

        // Degree 1
#pragma unroll
        for (int k = 0; k < 8; k++)
            accF(k, XA[k], XB[k]);

        // Degree 2 + 3 fused; pair products reused for triples.
        int f2 = 8, f3 = 44;
#pragma unroll
        for (int i = 0; i < 8; i++) {
#pragma unroll
            for (int j = i; j < 8; j++) {
                const u64 pA = mul2(XA[i], XA[j]);
                const u64 pB = mul2(XB[i], XB[j]);
                accF(f2, pA, pB);
                f2++;
#pragma unroll
                for (int k = j; k < 8; k++) {
                    accF(f3, mul2(pA, XA[k]), mul2(pB, XB[k]));
                    f3++;
                }
            }
        }

        // Store this half's 4 outputs for both units.
#pragma unroll
        for (int o = 0; o < 4; o++) {
            *(u64*)(out + gbase + (size_t)(pass * 4 + o) * HW) = accA[o];
            *(u64*)(out + gbase + bstr + (size_t)(pass * 4 + o) * HW) = accB[o];
        }
    }
}

extern "C" void kernel_launch(void* const* d_in, const int* in_sizes, int n_in,
                              void* d_out, int out_size)
{
    const float* x  = (const float*)d_in[0];
    const float* w1 = (const float*)d_in[1];
    const float* b1 = (const float*)d_in[2];
    const float* w2 = (const float*)d_in[3];
    const float* b2 = (const float*)d_in[4];
    const float* w3 = (const float*)d_in[5];
    const float* b3 = (const float*)d_in[6];

    dim3 grid(7, 32, 8);    // pixel-pair chunks, groups, batch pairs
    dim3 block(TPB);
    hoaf_kernel<<<grid, block>>>(x, w1, b1, w2, b2, w3, b3, (float*)d_out);
}

// round 12
// speedup vs baseline: 4.6593x; 4.6593x over previous
#include <cuda_runtime.h>

// HOAF: per-group (G=32, cpg=8) polynomial expansion (164 features) +
// per-group 8x164 matvec. B=16, C=256, HW=3136.
//
// R6: R2 (109us, best) is issue/latency-bound at 14 warps/SM (fma 54%, L1
// 53%, issue 38%). R5's register-rotating weight pipeline miscompiled
// (dynamic-index register array) -> wrong results. R3/R4: reg caps below
// ~110 with the full 8-output body spill catastrophically.
// This round: split the 8 outputs across BLOCKS (grid.y = group*2 + half),
// each block does 4 outputs x 2 pixel-units (batches z, z+8). Live set
// shrinks to ~90 regs => launch_bounds(224,3), 21 warps/SM. Same per-feature
// LDS:FMA shape as R2; +10.6% packed ops from deg2/3 muls recomputed per
// half. Predicted: occ ~31%, fma ~74%, ~85-90us.

typedef unsigned long long u64;

#define HW   3136
#define TPB  224

__device__ __forceinline__ u64 fma2(u64 a, u64 b, u64 c) {
    u64 d;
    asm("fma.rn.f32x2 %0, %1, %2, %3;" : "=l"(d) : "l"(a), "l"(b), "l"(c));
    return d;
}
__device__ __forceinline__ u64 mul2(u64 a, u64 b) {
    u64 d;
    asm("mul.rn.f32x2 %0, %1, %2;" : "=l"(d) : "l"(a), "l"(b));
    return d;
}

__global__ __launch_bounds__(TPB, 3) void hoaf_kernel(
    const float* __restrict__ x,
    const float* __restrict__ w1, const float* __restrict__ b1,
    const float* __restrict__ w2, const float* __restrict__ b2,
    const float* __restrict__ w3, const float* __restrict__ b3,
    float* __restrict__ out)
{
    // [feature][output-in-half], each entry (w,w) packed
    __shared__ alignas(16) u64 wdup[164][4];
    __shared__ u64 biasdup[4];

    const int tid  = threadIdx.x;
    const int g    = blockIdx.y >> 1;      // group
    const int half = blockIdx.y & 1;       // output half: outputs 4*half..+3

    // Stage this (group, half)'s weights, duplicated into both f32x2 lanes.
    // Feature f: [0,8)=deg1, [8,44)=deg2 (triu), [44,164)=deg3 (sorted
    // triples) -- identical ordering to the reference.
    for (int idx = tid; idx < 656; idx += TPB) {
        const int f  = idx >> 2;
        const int o  = half * 4 + (idx & 3);
        float v;
        if (f < 8)        v = w1[(g * 8 + o) * 8   + f];
        else if (f < 44)  v = w2[(g * 8 + o) * 36  + (f - 8)];
        else              v = w3[(g * 8 + o) * 120 + (f - 44)];
        const unsigned int u = __float_as_uint(v);
        wdup[f][idx & 3] = ((u64)u << 32) | u;
    }
    if (tid < 4) {
        const int o = half * 4 + tid;
        const float v = b1[g * 8 + o] + b2[g * 8 + o] + b3[g * 8 + o];
        const unsigned int u = __float_as_uint(v);
        biasdup[tid] = ((u64)u << 32) | u;
    }
    __syncthreads();

    // Pixel pair p in batches z and z+8.
    const int p = (blockIdx.x * TPB + tid) * 2;
    const size_t gbase = ((size_t)blockIdx.z * 256 + (size_t)g * 8) * HW + p;
    const size_t bstr  = (size_t)8 * 256 * HW;

    u64 XA[8], XB[8], accA[4], accB[4];
#pragma unroll
    for (int k = 0; k < 8; k++) {
        XA[k] = *(const u64*)(x + gbase + (size_t)k * HW);
        XB[k] = *(const u64*)(x + gbase + bstr + (size_t)k * HW);
    }
#pragma unroll
    for (int o = 0; o < 4; o++) { accA[o] = biasdup[o]; accB[o] = accA[o]; }

    // One feature (2 units) into this half's 4 outputs: 2 LDS.128, 8 FFMA2.
    auto accF = [&](int f, u64 fA, u64 fB) {
        const ulonglong2* wp = (const ulonglong2*)wdup[f];
        const ulonglong2 wa = wp[0], wb = wp[1];
        accA[0] = fma2(fA, wa.x, accA[0]);
        accB[0] = fma2(fB, wa.x, accB[0]);
        accA[1] = fma2(fA, wa.y, accA[1]);
        accB[1] = fma2(fB, wa.y, accB[1]);
        accA[2] = fma2(fA, wb.x, accA[2]);
        accB[2] = fma2(fB, wb.x, accB[2]);
        accA[3] = fma2(fA, wb.y, accA[3]);
        accB[3] = fma2(fB, wb.y, accB[3]);
    };

    // Degree 1
#pragma unroll
    for (int k = 0; k < 8; k++)
        accF(k, XA[k], XB[k]);

    // Degree 2 + 3 fused; pair products reused for triples.
    int f2 = 8, f3 = 44;
#pragma unroll
    for (int i = 0; i < 8; i++) {
#pragma unroll
        for (int j = i; j < 8; j++) {
            const u64 pA = mul2(XA[i], XA[j]);
            const u64 pB = mul2(XB[i], XB[j]);
            accF(f2, pA, pB);
            f2++;
#pragma unroll
            for (int k = j; k < 8; k++) {
                accF(f3, mul2(pA, XA[k]), mul2(pB, XB[k]));
                f3++;
            }
        }
    }

    // Store this half's 4 outputs for both units.
#pragma unroll
    for (int o = 0; o < 4; o++) {
        *(u64*)(out + gbase + (size_t)(half * 4 + o) * HW) = accA[o];
        *(u64*)(out + gbase + bstr + (size_t)(half * 4 + o) * HW) = accB[o];
    }
}

extern "C" void kernel_launch(void* const* d_in, const int* in_sizes, int n_in,
                              void* d_out, int out_size)
{
    const float* x  = (const float*)d_in[0];
    const float* w1 = (const float*)d_in[1];
    const float* b1 = (const float*)d_in[2];
    const float* w2 = (const float*)d_in[3];
    const float* b2 = (const float*)d_in[4];
    const float* w3 = (const float*)d_in[5];
    const float* b3 = (const float*)d_in[6];

    dim3 grid(7, 64, 8);    // pixel-pair chunks, group*half, batch pairs
    dim3 block(TPB);
    hoaf_kernel<<<grid, block>>>(x, w1, b1, w2, b2, w3, b3, (float*)d_out);
}